// round 15
// baseline (speedup 1.0000x reference)
#include <cuda_runtime.h>
#include <cuda_bf16.h>
#include <math.h>
#include <stdint.h>

#define NS   2
#define BSZ  4
#define LSEQ 1024
#define NTOK 4096
#define DM   512
#define DI   1024
#define DS   16
#define CIN  256
#define NCH  8
#define CHL  128

typedef __nv_bfloat16 bf16;
typedef unsigned long long u64;

// ---------------- scratch ----------------
__device__ bf16  d_xt[NS][NTOK * CIN];
__device__ bf16  d_seq[NS][NTOK * DM];
__device__ float d_ppart[NS][32][DM];
__device__ float d_lam[BSZ * 2];
__device__ bf16  d_xn[NS][NTOK * DM];
__device__ bf16  d_xp[NS][NTOK * 2 * DI];
__device__ bf16  d_u[NS][NTOK * DI];
__device__ bf16  d_wt[NS][DI * DM];
__device__ bf16  d_wc[NS][CIN * DI];
__device__ float d_wcp[8][CIN * DI];
__device__ bf16  d_crw[DM * CIN];
__device__ bf16  d_crsw[CIN * DM];
__device__ bf16  d_inw[NS][2 * DI * DM];
__device__ float d_hfin[NS * 2 * BSZ * NCH * DS * 1024];

// ---------------- PTX helpers ----------------
__device__ __forceinline__ uint32_t smem_u32(const void* p) {
    uint32_t a;
    asm("{ .reg .u64 t; cvta.to.shared.u64 t, %1; cvt.u32.u64 %0, t; }" : "=r"(a) : "l"(p));
    return a;
}
#define CP_ASYNC16(sp, gp) \
    asm volatile("cp.async.cg.shared.global [%0], [%1], 16;" :: "r"(sp), "l"(gp) : "memory")
#define CP_COMMIT() asm volatile("cp.async.commit_group;" ::: "memory")
#define CP_WAIT2()  asm volatile("cp.async.wait_group 2;" ::: "memory")

#define LDSM_X4(r0, r1, r2, r3, addr) \
    asm volatile("ldmatrix.sync.aligned.m8n8.x4.shared.b16 {%0,%1,%2,%3}, [%4];" \
                 : "=r"(r0), "=r"(r1), "=r"(r2), "=r"(r3) : "r"(addr))

#define MMA_BF16(d, a, b) \
    asm volatile("mma.sync.aligned.m16n8k16.row.col.f32.bf16.bf16.f32 " \
                 "{%0,%1,%2,%3}, {%4,%5,%6,%7}, {%8,%9}, {%0,%1,%2,%3};" \
                 : "+f"((d)[0]), "+f"((d)[1]), "+f"((d)[2]), "+f"((d)[3]) \
                 : "r"((a)[0]), "r"((a)[1]), "r"((a)[2]), "r"((a)[3]), \
                   "r"((b)[0]), "r"((b)[1]))

__device__ __forceinline__ u64 fma2_(u64 a, u64 b, u64 c) {
    u64 d;
    asm("fma.rn.f32x2 %0, %1, %2, %3;" : "=l"(d) : "l"(a), "l"(b), "l"(c));
    return d;
}
__device__ __forceinline__ u64 pack2(float lo, float hi) {
    u64 r;
    asm("mov.b64 %0, {%1, %2};" : "=l"(r) : "f"(lo), "f"(hi));
    return r;
}
__device__ __forceinline__ float2 unpack2(u64 v) {
    float2 f;
    asm("mov.b64 {%0, %1}, %2;" : "=f"(f.x), "=f"(f.y) : "l"(v));
    return f;
}

// ---------------- bf16 mma.sync GEMM: CTA 128x128, 128 threads, 2 CTAs/SM ----------------
#define TG_PITCH   80
#define TG_MATA    (128 * TG_PITCH)
#define TG_STAGE_B (2 * TG_MATA)
#define TG_NST     4
#define TG_SMEM    (TG_NST * TG_STAGE_B)

// EPI: 0 plain fp32, 1 BN+ReLU bf16 out + fused column pool, 2 bf16 out,
//      3 fused BN+residual+gate, smem-staged coalesced transposed out
template <int EPI>
__global__ void __launch_bounds__(128, 2)
tgemm(const bf16* __restrict__ A0, const bf16* __restrict__ A1,
      const bf16* __restrict__ B0, const bf16* __restrict__ B1,
      void* __restrict__ Cv, int M, int N, int K, int lda, int ldb, int zdiv,
      long long sCz,
      const float* __restrict__ eg, const float* __restrict__ eb,
      const float* __restrict__ em, const float* __restrict__ ev,
      const float* __restrict__ RX0, const float* __restrict__ RX1,
      const float* __restrict__ gp) {
    extern __shared__ float smf[];
    const uint32_t sbase = smem_u32(smf);

    const int tid  = threadIdx.x;
    const int lane = tid & 31;
    const int wid  = tid >> 5;
    const int z = blockIdx.z;
    const int zs = z / zdiv, kc = z % zdiv;
    const bf16* __restrict__ A = (zs ? A1 : A0) + (size_t)kc * K;
    const bf16* __restrict__ B = (zs ? B1 : B0) + (size_t)kc * K;
    const int m0 = blockIdx.y * 128, n0 = blockIdx.x * 128;
    const int wm = (wid >> 1) * 64;
    const int wn = (wid & 1) * 64;

    const int lr = tid >> 2;
    const int lc = tid & 3;
    const int T = K / 32;

    auto load_stage = [&](int t) {
        if (t < T) {
            const int k0 = t * 32;
            uint32_t dst = sbase + (t & 3) * TG_STAGE_B;
#pragma unroll
            for (int i = 0; i < 4; i++) {
                int m = lr + i * 32;
                CP_ASYNC16(dst + m * TG_PITCH + lc * 16,
                           A + (size_t)(m0 + m) * lda + k0 + lc * 8);
            }
            dst += TG_MATA;
#pragma unroll
            for (int i = 0; i < 4; i++) {
                int n = lr + i * 32;
                CP_ASYNC16(dst + n * TG_PITCH + lc * 16,
                           B + (size_t)(n0 + n) * ldb + k0 + lc * 8);
            }
        }
        CP_COMMIT();
    };

    float c[4][8][4];
#pragma unroll
    for (int mt = 0; mt < 4; mt++)
#pragma unroll
        for (int nt = 0; nt < 8; nt++)
#pragma unroll
            for (int q = 0; q < 4; q++) c[mt][nt][q] = 0.f;

    load_stage(0);
    load_stage(1);
    load_stage(2);

    const int l15   = lane & 15;
    const int lhiA  = (lane >> 4) * 16;
    const int bnrow = (lane & 7) + ((lane >> 4) << 3);
    const int bkoff = ((lane >> 3) & 1) * 16;

    for (int t = 0; t < T; t++) {
        CP_WAIT2();
        __syncthreads();
        load_stage(t + 3);
        const uint32_t aB = sbase + (t & 3) * TG_STAGE_B;
        const uint32_t bB = aB + TG_MATA;
#pragma unroll
        for (int kk = 0; kk < 2; kk++) {
            uint32_t a[4][4], b[8][2];
#pragma unroll
            for (int mt = 0; mt < 4; mt++) {
                uint32_t addr = aB + (wm + mt * 16 + l15) * TG_PITCH + kk * 32 + lhiA;
                LDSM_X4(a[mt][0], a[mt][1], a[mt][2], a[mt][3], addr);
            }
#pragma unroll
            for (int nh = 0; nh < 4; nh++) {
                uint32_t addr = bB + (wn + nh * 16 + bnrow) * TG_PITCH + kk * 32 + bkoff;
                uint32_t r0, r1, r2, r3;
                LDSM_X4(r0, r1, r2, r3, addr);
                b[nh * 2][0] = r0; b[nh * 2][1] = r1;
                b[nh * 2 + 1][0] = r2; b[nh * 2 + 1][1] = r3;
            }
#pragma unroll
            for (int mt = 0; mt < 4; mt++)
#pragma unroll
                for (int nt = 0; nt < 8; nt++)
                    MMA_BF16(c[mt][nt], a[mt], b[nt]);
        }
    }

    const int gid = lane >> 2;
    const int tig = lane & 3;

    if (EPI == 3) {
        // stage raw accumulators to smem [col][tok] (pitch 132), then coalesced writeback
        __syncthreads();
        float* st = smf;
#pragma unroll
        for (int mt = 0; mt < 4; mt++) {
            int r = wm + mt * 16 + gid;
#pragma unroll
            for (int nt = 0; nt < 8; nt++) {
                int cc = wn + nt * 8 + tig * 2;
                st[cc * 132 + r]           = c[mt][nt][0];
                st[(cc + 1) * 132 + r]     = c[mt][nt][1];
                st[cc * 132 + r + 8]       = c[mt][nt][2];
                st[(cc + 1) * 132 + r + 8] = c[mt][nt][3];
            }
        }
        __syncthreads();
        float sg = 1.f / (1.f + expf(-gp[0]));
        int col = n0 + tid;
        float s0 = eg[col] * rsqrtf(ev[col] + 1e-5f);
        float h0 = eb[col] - em[col] * s0;
        const float* xin = zs ? RX1 : RX0;
        float* outp = (float*)Cv + (size_t)zs * BSZ * CIN * LSEQ;
        int b = m0 >> 10, hw0 = m0 & 1023;
        size_t gbase = ((size_t)b * CIN + col) * LSEQ + hw0;
        const float* sp = st + tid * 132;
#pragma unroll 4
        for (int q = 0; q < 32; q++) {
            float4 xi = *(const float4*)&xin[gbase + q * 4];
            float4 vv = *(const float4*)&sp[q * 4];
            float4 o;
            o.x = xi.x + sg * (vv.x * s0 + h0);
            o.y = xi.y + sg * (vv.y * s0 + h0);
            o.z = xi.z + sg * (vv.z * s0 + h0);
            o.w = xi.w + sg * (vv.w * s0 + h0);
            *(float4*)&outp[gbase + q * 4] = o;
        }
        return;
    }

    float cs[16];
    if (EPI == 1) {
#pragma unroll
        for (int i = 0; i < 16; i++) cs[i] = 0.f;
    }
#pragma unroll
    for (int mt = 0; mt < 4; mt++) {
        const int r0 = m0 + wm + mt * 16 + gid;
#pragma unroll
        for (int nt = 0; nt < 8; nt++) {
            const int col = n0 + wn + nt * 8 + tig * 2;
            float v0 = c[mt][nt][0], v1 = c[mt][nt][1];
            float v2 = c[mt][nt][2], v3 = c[mt][nt][3];
            if (EPI == 1) {
                float s0 = eg[col] * rsqrtf(ev[col] + 1e-5f);
                float h0 = eb[col] - em[col] * s0;
                float s1 = eg[col + 1] * rsqrtf(ev[col + 1] + 1e-5f);
                float h1 = eb[col + 1] - em[col + 1] * s1;
                v0 = fmaxf(v0 * s0 + h0, 0.f);
                v1 = fmaxf(v1 * s1 + h1, 0.f);
                v2 = fmaxf(v2 * s0 + h0, 0.f);
                v3 = fmaxf(v3 * s1 + h1, 0.f);
                cs[nt * 2]     += v0 + v2;
                cs[nt * 2 + 1] += v1 + v3;
                bf16* Cb = (bf16*)Cv + (size_t)z * sCz;
                *(__nv_bfloat162*)&Cb[(size_t)r0 * N + col] =
                    __floats2bfloat162_rn(v0, v1);
                *(__nv_bfloat162*)&Cb[(size_t)(r0 + 8) * N + col] =
                    __floats2bfloat162_rn(v2, v3);
            } else if (EPI == 2) {
                bf16* Cb = (bf16*)Cv + (size_t)z * sCz;
                *(__nv_bfloat162*)&Cb[(size_t)r0 * N + col] =
                    __floats2bfloat162_rn(v0, v1);
                *(__nv_bfloat162*)&Cb[(size_t)(r0 + 8) * N + col] =
                    __floats2bfloat162_rn(v2, v3);
            } else {
                float* Cf = (float*)Cv + (size_t)z * sCz;
                *(float2*)&Cf[(size_t)r0 * N + col]       = make_float2(v0, v1);
                *(float2*)&Cf[(size_t)(r0 + 8) * N + col] = make_float2(v2, v3);
            }
        }
    }

    if (EPI == 1) {
#pragma unroll
        for (int off = 4; off <= 16; off <<= 1)
#pragma unroll
            for (int i = 0; i < 16; i++)
                cs[i] += __shfl_xor_sync(0xffffffffu, cs[i], off);
        __syncthreads();
        float* scol = smf;
        if (wid < 2 && lane < 4) {
#pragma unroll
            for (int nt = 0; nt < 8; nt++) {
                scol[wn + nt * 8 + lane * 2]     = cs[nt * 2];
                scol[wn + nt * 8 + lane * 2 + 1] = cs[nt * 2 + 1];
            }
        }
        __syncthreads();
        if (wid >= 2 && lane < 4) {
#pragma unroll
            for (int nt = 0; nt < 8; nt++) {
                scol[wn + nt * 8 + lane * 2]     += cs[nt * 2];
                scol[wn + nt * 8 + lane * 2 + 1] += cs[nt * 2 + 1];
            }
        }
        __syncthreads();
        d_ppart[zs][m0 >> 7][n0 + tid] = scol[tid];
    }
}

// ---------------- mega prep ----------------
#define PREP_N (DM * CIN + CIN * DM + 2 * (2 * DI * DM))
#define NB_PREP (PREP_N / 256)
#define NB_TIN  (32 * 8 * 8)
#define NB_TW   (32 * 16 * 2)
__global__ void __launch_bounds__(256)
mega_prep(const float* __restrict__ crw, const float* __restrict__ crsw,
          const float* __restrict__ iw0, const float* __restrict__ iw1,
          const float* __restrict__ x0, const float* __restrict__ x1,
          const float* __restrict__ ow0, const float* __restrict__ ow1) {
    int bid = blockIdx.x;
    int tid = threadIdx.x;
    if (bid < NB_PREP) {
        int i = bid * 256 + tid;
        const int n1 = DM * CIN, n2 = n1 + CIN * DM, n3 = n2 + 2 * DI * DM;
        if (i < n1)       d_crw[i]           = __float2bfloat16(crw[i]);
        else if (i < n2)  d_crsw[i - n1]     = __float2bfloat16(crsw[i - n1]);
        else if (i < n3)  d_inw[0][i - n2]   = __float2bfloat16(iw0[i - n2]);
        else              d_inw[1][i - n3]   = __float2bfloat16(iw1[i - n3]);
    } else if (bid < NB_PREP + NB_TIN) {
        __shared__ float tile[32][33];
        int q = bid - NB_PREP;
        int zc = q >> 8;
        int s = zc >> 2, b = zc & 3;
        int rem = q & 255;
        int c0 = (rem >> 5) * 32, hw0 = (rem & 31) * 32;
        const float* x = s ? x1 : x0;
        int tx = tid & 31, ty = tid >> 5;
#pragma unroll
        for (int r = 0; r < 4; r++) {
            int row = ty + r * 8;
            tile[row][tx] = x[((size_t)b * CIN + (c0 + row)) * LSEQ + hw0 + tx];
        }
        __syncthreads();
#pragma unroll
        for (int r = 0; r < 4; r++) {
            int row = ty + r * 8;
            d_xt[s][((size_t)b * LSEQ + hw0 + row) * CIN + c0 + tx] =
                __float2bfloat16(tile[tx][row]);
        }
    } else {
        __shared__ float tile[32][33];
        int q = bid - NB_PREP - NB_TIN;
        int s = q >> 9;
        int rem = q & 511;
        int r0 = (rem >> 5) * 32, c0 = (rem & 31) * 32;
        const float* w = s ? ow1 : ow0;
        int tx = tid & 31, ty = tid >> 5;
#pragma unroll
        for (int r = 0; r < 4; r++) {
            int row = ty + r * 8;
            tile[row][tx] = w[(size_t)(r0 + row) * DI + c0 + tx];
        }
        __syncthreads();
#pragma unroll
        for (int r = 0; r < 4; r++) {
            int row = ty + r * 8;
            d_wt[s][(size_t)(c0 + row) * DM + r0 + tx] = __float2bfloat16(tile[tx][row]);
        }
    }
}

// ---------------- layernorm (warp-per-token) + wc_reduce ----------------
#define NB_LN  (2 * NTOK / 4)                // 2048
#define NB_WCR (2 * CIN * DI / 128)          // 4096
__global__ void __launch_bounds__(128)
poolln(const float* __restrict__ g0, const float* __restrict__ b0,
       const float* __restrict__ g1, const float* __restrict__ b1) {
    int bid = blockIdx.x;
    int t = threadIdx.x;
    if (bid < NB_LN) {
        int wid = t >> 5, lane = t & 31;
        int tok = bid * 4 + wid;             // 0..8191
        int s = tok >> 12;
        int n = tok & (NTOK - 1);
        const float* g = s ? g1 : g0;
        const float* b = s ? b1 : b0;
        const __nv_bfloat162* src = (const __nv_bfloat162*)(d_seq[s] + (size_t)n * DM);
        float2 v[8];
        float sm = 0.f, sq = 0.f;
#pragma unroll
        for (int j = 0; j < 8; j++) {
            v[j] = __bfloat1622float2(src[lane + 32 * j]);
            sm += v[j].x + v[j].y;
            sq += v[j].x * v[j].x + v[j].y * v[j].y;
        }
#pragma unroll
        for (int o = 16; o; o >>= 1) {
            sm += __shfl_xor_sync(0xffffffffu, sm, o);
            sq += __shfl_xor_sync(0xffffffffu, sq, o);
        }
        float mu = sm * (1.f / DM);
        float var = sq * (1.f / DM) - mu * mu;
        float inv = rsqrtf(var + 1e-5f);
        __nv_bfloat162* dst = (__nv_bfloat162*)(d_xn[s] + (size_t)n * DM);
#pragma unroll
        for (int j = 0; j < 8; j++) {
            int p = lane + 32 * j;
            float2 gg = *(const float2*)&g[2 * p];
            float2 bb = *(const float2*)&b[2 * p];
            dst[p] = __floats2bfloat162_rn((v[j].x - mu) * inv * gg.x + bb.x,
                                           (v[j].y - mu) * inv * gg.y + bb.y);
        }
    } else {
        int idx = (bid - NB_LN) * 128 + t;
        int s = idx >> 18;
        int j = idx & (CIN * DI - 1);
        float v = d_wcp[s * 4 + 0][j] + d_wcp[s * 4 + 1][j] +
                  d_wcp[s * 4 + 2][j] + d_wcp[s * 4 + 3][j];
        d_wc[s][j] = __float2bfloat16(v);
    }
}

// ---------------- lambda predictor ----------------
__global__ void lambda_kernel(const float* __restrict__ w1, const float* __restrict__ b1,
                              const float* __restrict__ w2, const float* __restrict__ b2) {
    int b = blockIdx.x, j = threadIdx.x;
    __shared__ float pooled[2 * DM];
    for (int idx = j; idx < 2 * DM; idx += 128) {
        int s = idx >> 9, d = idx & (DM - 1);
        float acc = 0.f;
#pragma unroll
        for (int c = 0; c < 8; c++) acc += d_ppart[s][b * 8 + c][d];
        pooled[idx] = acc * (1.0f / LSEQ);
    }
    __syncthreads();
    const float* w = w1 + (size_t)j * (2 * DM);
    float acc = b1[j];
    for (int c = 0; c < DM; c++) acc += pooled[c] * w[c];
    for (int c = 0; c < DM; c++) acc += pooled[DM + c] * w[DM + c];
    __shared__ float h1[128];
    h1[j] = fmaxf(acc, 0.f);
    __syncthreads();
    if (j == 0) {
        float l0 = b2[0], l1 = b2[1];
        for (int c = 0; c < 128; c++) { l0 += h1[c] * w2[c]; l1 += h1[c] * w2[128 + c]; }
        float mx = fmaxf(l0, l1);
        float e0 = expf(l0 - mx), e1 = expf(l1 - mx);
        float inv = 1.f / (e0 + e1);
        d_lam[b * 2 + 0] = e0 * inv;
        d_lam[b * 2 + 1] = e1 * inv;
    }
}

// ================= chunked parallel scan =================
__device__ __forceinline__ size_t hf_off(int s, int dir, int b, int c, int i) {
    return (((((size_t)s * 2 + dir) * 4 + b) * NCH + c) * DS) * 1024 + i;
}

__global__ void __launch_bounds__(256)
scan_pass1(const float* __restrict__ VA, const float* __restrict__ VB,
           const float* __restrict__ IA, const float* __restrict__ IB) {
    int idx = blockIdx.x * 256 + threadIdx.x;
    int i   = idx & 1023;
    int r   = idx >> 10;
    int c   = r % 7;
    int r2  = r / 7;
    int b   = r2 & 3;
    int dir = (r2 >> 2) & 1;
    int s   = (r2 >> 3) & 1;

    const float* Alog = s ? IA : VA;
    const float* Bown = s ? IB : VB;
    const float* Both = s ? VB : IB;
    float w0 = 0.5f * d_lam[b * 2 + 0];
    float w1 = 0.5f * d_lam[b * 2 + 1];

    u64 A2[8], Be2[8], h2[8];
#pragma unroll
    for (int k = 0; k < 8; k++) {
        float a0 = fminf(fmaxf(-expf(Alog[i * DS + 2 * k]),     -10.f), -0.01f);
        float a1 = fminf(fmaxf(-expf(Alog[i * DS + 2 * k + 1]), -10.f), -0.01f);
        A2[k]  = pack2(a0, a1);
        Be2[k] = pack2(w0 * Bown[i * DS + 2 * k]     + w1 * Both[i * DS + 2 * k],
                       w0 * Bown[i * DS + 2 * k + 1] + w1 * Both[i * DS + 2 * k + 1]);
        h2[k] = 0ull;
    }

    const bf16* xs = d_xp[s] + (size_t)b * LSEQ * (2 * DI) + i;
    int t  = dir ? (LSEQ - 1 - c * CHL) : c * CHL;
    int dt = dir ? -1 : 1;

    for (int step = 0; step < CHL; step++, t += dt) {
        float x = __bfloat162float(xs[(size_t)t * (2 * DI)]);
        u64 xd = pack2(x, x);
#pragma unroll
        for (int k = 0; k < 8; k++)
            h2[k] = fma2_(h2[k], A2[k], fma2_(Be2[k], xd, 0ull));
    }

    size_t o0 = hf_off(s, dir, b, c, i);
#pragma unroll
    for (int k = 0; k < 8; k++) {
        float2 f = unpack2(h2[k]);
        d_hfin[o0 + (size_t)(2 * k) * 1024]     = f.x;
        d_hfin[o0 + (size_t)(2 * k + 1) * 1024] = f.y;
    }
}

__global__ void __launch_bounds__(256, 2)
scan_pass3m(const float* __restrict__ VA, const float* __restrict__ VB,
            const float* __restrict__ VC, const float* __restrict__ IA,
            const float* __restrict__ IB, const float* __restrict__ IC) {
    extern __shared__ bf16 yfs[];
    int tid = threadIdx.x;
    int idx = blockIdx.x * 256 + tid;
    int i   = idx & 1023;
    int c   = (idx >> 10) & 7;
    int b   = (idx >> 13) & 3;
    int s   = (idx >> 14) & 1;

    const float* Alog = s ? IA : VA;
    const float* Bown = s ? IB : VB;
    const float* Both = s ? VB : IB;
    const float* Cp   = s ? IC : VC;
    float w0 = 0.5f * d_lam[b * 2 + 0];
    float w1 = 0.5f * d_lam[b * 2 + 1];

    u64 A2[8], Be2[8], C2[8], h2[8];
#pragma unroll
    for (int k = 0; k < 8; k++) {
        float a0 = fminf(fmaxf(-expf(Alog[i * DS + 2 * k]),     -10.f), -0.01f);
        float a1 = fminf(fmaxf(-expf(Alog[i * DS + 2 * k + 1]), -10.f), -0.01f);
        A2[k]  = pack2(a0, a1);
        Be2[k] = pack2(w0 * Bown[i * DS + 2 * k]     + w1 * Both[i * DS + 2 * k],
                       w0 * Bown[i * DS + 2 * k + 1] + w1 * Both[i * DS + 2 * k + 1]);
        C2[k]  = pack2(Cp[i * DS + 2 * k], Cp[i * DS + 2 * k + 1]);
    }

    u64 a128[8];
#pragma unroll
    for (int k = 0; k < 8; k++) {
        u64 a = A2[k];
#pragma unroll
        for (int q = 0; q < 7; q++) a = fma2_(a, a, 0ull);
        a128[k] = a;
    }

    const bf16* xs = d_xp[s] + (size_t)b * LSEQ * (2 * DI) + i;
    const bf16* gs = xs + DI;
    bf16* uo = d_u[s] + (size_t)b * LSEQ * DI + i;
    const int t0 = c * CHL;
    const int cb = NCH - 1 - c;

    {
#pragma unroll
        for (int k = 0; k < 8; k++) h2[k] = 0ull;
        for (int cc = 0; cc < c; cc++) {
            size_t o = hf_off(s, 0, b, cc, i);
#pragma unroll
            for (int k = 0; k < 8; k++) {
                u64 fin = pack2(d_hfin[o + (size_t)(2 * k) * 1024],
                                d_hfin[o + (size_t)(2 * k + 1) * 1024]);
                h2[k] = fma2_(h2[k], a128[k], fin);
            }
        }
        for (int step = 0; step < CHL; step++) {
            float x = __bfloat162float(xs[(size_t)(t0 + step) * (2 * DI)]);
            u64 xd = pack2(x, x);
            u64 yp = 0ull;
#pragma unroll
            for (int k = 0; k < 8; k++) {
                h2[k] = fma2_(h2[k], A2[k], fma2_(Be2[k], xd, 0ull));
                yp = fma2_(h2[k], C2[k], yp);
            }
            float2 f = unpack2(yp);
            yfs[step * 256 + tid] = __float2bfloat16(f.x + f.y);
        }
    }
    {
#pragma unroll
        for (int k = 0; k < 8; k++) h2[k] = 0ull;
        for (int cc = 0; cc < cb; cc++) {
            size_t o = hf_off(s, 1, b, cc, i);
#pragma unroll
            for (int k = 0; k < 8; k++) {
                u64 fin = pack2(d_hfin[o + (size_t)(2 * k) * 1024],
                                d_hfin[o + (size_t)(2 * k + 1) * 1024]);
                h2[k] = fma2_(h2[k], a128[k], fin);
            }
        }
        for (int step = 0; step < CHL; step++) {
            int ls = CHL - 1 - step;
            int t = t0 + ls;
            float x = __bfloat162float(xs[(size_t)t * (2 * DI)]);
            u64 xd = pack2(x, x);
            u64 yp = 0ull;
#pragma unroll
            for (int k = 0; k < 8; k++) {
                h2[k] = fma2_(h2[k], A2[k], fma2_(Be2[k], xd, 0ull));
                yp = fma2_(h2[k], C2[k], yp);
            }
            float2 f = unpack2(yp);
            float yb = f.x + f.y;
            float yf = __bfloat162float(yfs[ls * 256 + tid]);
            float g = __bfloat162float(gs[(size_t)t * (2 * DI)]);
            float sig = 1.f / (1.f + expf(-g));
            uo[(size_t)t * DI] = __float2bfloat16((yf + yb) * g * sig);
        }
    }
}

// ---------------- launch ----------------
extern "C" void kernel_launch(void* const* d_in, const int* in_sizes, int n_in,
                              void* d_out, int out_size) {
    const float* x_V        = (const float*)d_in[0];
    const float* x_I        = (const float*)d_in[1];
    const float* conv_red_w = (const float*)d_in[2];
    const float* bn_red_g   = (const float*)d_in[3];
    const float* bn_red_b   = (const float*)d_in[4];
    const float* bn_red_m   = (const float*)d_in[5];
    const float* bn_red_v   = (const float*)d_in[6];
    const float* conv_res_w = (const float*)d_in[7];
    const float* bn_res_g   = (const float*)d_in[8];
    const float* bn_res_b   = (const float*)d_in[9];
    const float* bn_res_m   = (const float*)d_in[10];
    const float* bn_res_v   = (const float*)d_in[11];
    const float* lam_w1     = (const float*)d_in[12];
    const float* lam_b1     = (const float*)d_in[13];
    const float* lam_w2     = (const float*)d_in[14];
    const float* lam_b2     = (const float*)d_in[15];
    const float* in_w[2]    = {(const float*)d_in[16], (const float*)d_in[23]};
    const float* out_w[2]   = {(const float*)d_in[17], (const float*)d_in[24]};
    const float* A_log[2]   = {(const float*)d_in[18], (const float*)d_in[25]};
    const float* Bmat[2]    = {(const float*)d_in[19], (const float*)d_in[26]};
    const float* Cmat[2]    = {(const float*)d_in[20], (const float*)d_in[27]};
    const float* ln_g[2]    = {(const float*)d_in[21], (const float*)d_in[28]};
    const float* ln_b[2]    = {(const float*)d_in[22], (const float*)d_in[29]};
    const float* gate       = (const float*)d_in[30];

    bf16 *XT, *SEQ, *XN, *XP, *U, *WT, *WC, *CRW, *CRSW, *INW;
    float *WCP;
    cudaGetSymbolAddress((void**)&XT,   d_xt);
    cudaGetSymbolAddress((void**)&SEQ,  d_seq);
    cudaGetSymbolAddress((void**)&XN,   d_xn);
    cudaGetSymbolAddress((void**)&XP,   d_xp);
    cudaGetSymbolAddress((void**)&U,    d_u);
    cudaGetSymbolAddress((void**)&WT,   d_wt);
    cudaGetSymbolAddress((void**)&WC,   d_wc);
    cudaGetSymbolAddress((void**)&WCP,  d_wcp);
    cudaGetSymbolAddress((void**)&CRW,  d_crw);
    cudaGetSymbolAddress((void**)&CRSW, d_crsw);
    cudaGetSymbolAddress((void**)&INW,  d_inw);

    cudaFuncSetAttribute(tgemm<0>, cudaFuncAttributeMaxDynamicSharedMemorySize, TG_SMEM);
    cudaFuncSetAttribute(tgemm<1>, cudaFuncAttributeMaxDynamicSharedMemorySize, TG_SMEM);
    cudaFuncSetAttribute(tgemm<2>, cudaFuncAttributeMaxDynamicSharedMemorySize, TG_SMEM);
    cudaFuncSetAttribute(tgemm<3>, cudaFuncAttributeMaxDynamicSharedMemorySize, TG_SMEM);
    cudaFuncSetAttribute(scan_pass3m, cudaFuncAttributeMaxDynamicSharedMemorySize, 65536);

    // 0. mega prep
    mega_prep<<<NB_PREP + NB_TIN + NB_TW, 256>>>(
        conv_red_w, conv_res_w, in_w[0], in_w[1], x_V, x_I, out_w[0], out_w[1]);

    // 1. Wc split-K x4 (reduce folded into poolln)
    tgemm<0><<<dim3(DI / 128, CIN / 128, 8), 128, TG_SMEM>>>(
        CRSW, CRSW, WT, WT + (size_t)DI * DM, WCP, CIN, DI, DM / 4, DM, DM, 4,
        (long long)CIN * DI, nullptr, nullptr, nullptr, nullptr,
        nullptr, nullptr, nullptr);

    // 2. conv_red + BN + ReLU -> bf16 d_seq (+ fused column pool partials)
    tgemm<1><<<dim3(DM / 128, NTOK / 128, 2), 128, TG_SMEM>>>(
        XT, XT + (size_t)NTOK * CIN, CRW, CRW, SEQ, NTOK, DM, CIN, CIN, CIN, 1,
        (long long)NTOK * DM, bn_red_g, bn_red_b, bn_red_m, bn_red_v,
        nullptr, nullptr, nullptr);

    // 3. layernorm (warp/token) + wc_reduce, then lambda
    poolln<<<NB_LN + NB_WCR, 128>>>(ln_g[0], ln_b[0], ln_g[1], ln_b[1]);
    lambda_kernel<<<4, 128>>>(lam_w1, lam_b1, lam_w2, lam_b2);

    // 4. in_proj (bf16 out)
    tgemm<2><<<dim3(2 * DI / 128, NTOK / 128, 2), 128, TG_SMEM>>>(
        XN, XN + (size_t)NTOK * DM, INW, INW + (size_t)2 * DI * DM, XP, NTOK, 2 * DI,
        DM, DM, DM, 1, (long long)NTOK * 2 * DI, nullptr, nullptr, nullptr, nullptr,
        nullptr, nullptr, nullptr);

    // 5. scan
    scan_pass1<<<448, 256>>>(A_log[0], Bmat[0], A_log[1], Bmat[1]);
    scan_pass3m<<<256, 256, 65536>>>(A_log[0], Bmat[0], Cmat[0],
                                     A_log[1], Bmat[1], Cmat[1]);

    // 6. fused out_proj + conv_res + BN + residual + gate -> output (coalesced)
    tgemm<3><<<dim3(CIN / 128, NTOK / 128, 2), 128, TG_SMEM>>>(
        U, U + (size_t)NTOK * DI, WC, WC + (size_t)CIN * DI, (float*)d_out, NTOK, CIN,
        DI, DI, DI, 1, 0LL, bn_res_g, bn_res_b, bn_res_m, bn_res_v,
        x_V, x_I, gate);
}

// round 16
// speedup vs baseline: 1.0140x; 1.0140x over previous
#include <cuda_runtime.h>
#include <cuda_bf16.h>
#include <math.h>
#include <stdint.h>

#define NS   2
#define BSZ  4
#define LSEQ 1024
#define NTOK 4096
#define DM   512
#define DI   1024
#define DS   16
#define CIN  256
#define NCH  8
#define CHL  128

typedef __nv_bfloat16 bf16;
typedef unsigned long long u64;

// ---------------- scratch ----------------
__device__ bf16  d_xt[NS][NTOK * CIN];
__device__ bf16  d_seq[NS][NTOK * DM];
__device__ float d_ppart[NS][32][DM];
__device__ float d_lam[BSZ * 2];
__device__ bf16  d_xn[NS][NTOK * DM];
__device__ bf16  d_xp[NS][NTOK * 2 * DI];
__device__ bf16  d_u[NS][NTOK * DI];
__device__ bf16  d_wt[NS][DI * DM];
__device__ bf16  d_wc[NS][CIN * DI];
__device__ float d_wcp[8][CIN * DI];
__device__ bf16  d_crw[DM * CIN];
__device__ bf16  d_crsw[CIN * DM];
__device__ bf16  d_inw[NS][2 * DI * DM];
__device__ float d_hfin[NS * 2 * BSZ * NCH * DS * 1024];

// ---------------- PTX helpers ----------------
__device__ __forceinline__ uint32_t smem_u32(const void* p) {
    uint32_t a;
    asm("{ .reg .u64 t; cvta.to.shared.u64 t, %1; cvt.u32.u64 %0, t; }" : "=r"(a) : "l"(p));
    return a;
}
#define CP_ASYNC16(sp, gp) \
    asm volatile("cp.async.cg.shared.global [%0], [%1], 16;" :: "r"(sp), "l"(gp) : "memory")
#define CP_COMMIT() asm volatile("cp.async.commit_group;" ::: "memory")
#define CP_WAIT2()  asm volatile("cp.async.wait_group 2;" ::: "memory")

#define LDSM_X4(r0, r1, r2, r3, addr) \
    asm volatile("ldmatrix.sync.aligned.m8n8.x4.shared.b16 {%0,%1,%2,%3}, [%4];" \
                 : "=r"(r0), "=r"(r1), "=r"(r2), "=r"(r3) : "r"(addr))

#define MMA_BF16(d, a, b) \
    asm volatile("mma.sync.aligned.m16n8k16.row.col.f32.bf16.bf16.f32 " \
                 "{%0,%1,%2,%3}, {%4,%5,%6,%7}, {%8,%9}, {%0,%1,%2,%3};" \
                 : "+f"((d)[0]), "+f"((d)[1]), "+f"((d)[2]), "+f"((d)[3]) \
                 : "r"((a)[0]), "r"((a)[1]), "r"((a)[2]), "r"((a)[3]), \
                   "r"((b)[0]), "r"((b)[1]))

__device__ __forceinline__ u64 fma2_(u64 a, u64 b, u64 c) {
    u64 d;
    asm("fma.rn.f32x2 %0, %1, %2, %3;" : "=l"(d) : "l"(a), "l"(b), "l"(c));
    return d;
}
__device__ __forceinline__ u64 pack2(float lo, float hi) {
    u64 r;
    asm("mov.b64 %0, {%1, %2};" : "=l"(r) : "f"(lo), "f"(hi));
    return r;
}
__device__ __forceinline__ float2 unpack2(u64 v) {
    float2 f;
    asm("mov.b64 {%0, %1}, %2;" : "=f"(f.x), "=f"(f.y) : "l"(v));
    return f;
}

// ---------------- bf16 mma.sync GEMM: CTA 128x128, 128 threads, 2 CTAs/SM ----------------
#define TG_PITCH   80
#define TG_MATA    (128 * TG_PITCH)
#define TG_STAGE_B (2 * TG_MATA)
#define TG_NST     4
#define TG_SMEM    (TG_NST * TG_STAGE_B)

// EPI: 0 plain fp32, 1 BN+ReLU bf16 out + fused column pool, 2 bf16 out,
//      3 fused BN+residual+gate transposed out (direct scatter)
template <int EPI>
__global__ void __launch_bounds__(128, 2)
tgemm(const bf16* __restrict__ A0, const bf16* __restrict__ A1,
      const bf16* __restrict__ B0, const bf16* __restrict__ B1,
      void* __restrict__ Cv, int M, int N, int K, int lda, int ldb, int zdiv,
      long long sCz,
      const float* __restrict__ eg, const float* __restrict__ eb,
      const float* __restrict__ em, const float* __restrict__ ev,
      const float* __restrict__ RX0, const float* __restrict__ RX1,
      const float* __restrict__ gp) {
    extern __shared__ float smf[];
    const uint32_t sbase = smem_u32(smf);

    const int tid  = threadIdx.x;
    const int lane = tid & 31;
    const int wid  = tid >> 5;
    const int z = blockIdx.z;
    const int zs = z / zdiv, kc = z % zdiv;
    const bf16* __restrict__ A = (zs ? A1 : A0) + (size_t)kc * K;
    const bf16* __restrict__ B = (zs ? B1 : B0) + (size_t)kc * K;
    const int m0 = blockIdx.y * 128, n0 = blockIdx.x * 128;
    const int wm = (wid >> 1) * 64;
    const int wn = (wid & 1) * 64;

    const int lr = tid >> 2;
    const int lc = tid & 3;
    const int T = K / 32;

    auto load_stage = [&](int t) {
        if (t < T) {
            const int k0 = t * 32;
            uint32_t dst = sbase + (t & 3) * TG_STAGE_B;
#pragma unroll
            for (int i = 0; i < 4; i++) {
                int m = lr + i * 32;
                CP_ASYNC16(dst + m * TG_PITCH + lc * 16,
                           A + (size_t)(m0 + m) * lda + k0 + lc * 8);
            }
            dst += TG_MATA;
#pragma unroll
            for (int i = 0; i < 4; i++) {
                int n = lr + i * 32;
                CP_ASYNC16(dst + n * TG_PITCH + lc * 16,
                           B + (size_t)(n0 + n) * ldb + k0 + lc * 8);
            }
        }
        CP_COMMIT();
    };

    float c[4][8][4];
#pragma unroll
    for (int mt = 0; mt < 4; mt++)
#pragma unroll
        for (int nt = 0; nt < 8; nt++)
#pragma unroll
            for (int q = 0; q < 4; q++) c[mt][nt][q] = 0.f;

    load_stage(0);
    load_stage(1);
    load_stage(2);

    const int l15   = lane & 15;
    const int lhiA  = (lane >> 4) * 16;
    const int bnrow = (lane & 7) + ((lane >> 4) << 3);
    const int bkoff = ((lane >> 3) & 1) * 16;

    for (int t = 0; t < T; t++) {
        CP_WAIT2();
        __syncthreads();
        load_stage(t + 3);
        const uint32_t aB = sbase + (t & 3) * TG_STAGE_B;
        const uint32_t bB = aB + TG_MATA;
#pragma unroll
        for (int kk = 0; kk < 2; kk++) {
            uint32_t a[4][4], b[8][2];
#pragma unroll
            for (int mt = 0; mt < 4; mt++) {
                uint32_t addr = aB + (wm + mt * 16 + l15) * TG_PITCH + kk * 32 + lhiA;
                LDSM_X4(a[mt][0], a[mt][1], a[mt][2], a[mt][3], addr);
            }
#pragma unroll
            for (int nh = 0; nh < 4; nh++) {
                uint32_t addr = bB + (wn + nh * 16 + bnrow) * TG_PITCH + kk * 32 + bkoff;
                uint32_t r0, r1, r2, r3;
                LDSM_X4(r0, r1, r2, r3, addr);
                b[nh * 2][0] = r0; b[nh * 2][1] = r1;
                b[nh * 2 + 1][0] = r2; b[nh * 2 + 1][1] = r3;
            }
#pragma unroll
            for (int mt = 0; mt < 4; mt++)
#pragma unroll
                for (int nt = 0; nt < 8; nt++)
                    MMA_BF16(c[mt][nt], a[mt], b[nt]);
        }
    }

    const int gid = lane >> 2;
    const int tig = lane & 3;
    float sg = 0.f;
    if (EPI == 3) sg = 1.f / (1.f + expf(-gp[0]));
    float cs[16];
    if (EPI == 1) {
#pragma unroll
        for (int i = 0; i < 16; i++) cs[i] = 0.f;
    }
#pragma unroll
    for (int mt = 0; mt < 4; mt++) {
        const int r0 = m0 + wm + mt * 16 + gid;
#pragma unroll
        for (int nt = 0; nt < 8; nt++) {
            const int col = n0 + wn + nt * 8 + tig * 2;
            float v0 = c[mt][nt][0], v1 = c[mt][nt][1];
            float v2 = c[mt][nt][2], v3 = c[mt][nt][3];
            if (EPI == 1) {
                float s0 = eg[col] * rsqrtf(ev[col] + 1e-5f);
                float h0 = eb[col] - em[col] * s0;
                float s1 = eg[col + 1] * rsqrtf(ev[col + 1] + 1e-5f);
                float h1 = eb[col + 1] - em[col + 1] * s1;
                v0 = fmaxf(v0 * s0 + h0, 0.f);
                v1 = fmaxf(v1 * s1 + h1, 0.f);
                v2 = fmaxf(v2 * s0 + h0, 0.f);
                v3 = fmaxf(v3 * s1 + h1, 0.f);
                cs[nt * 2]     += v0 + v2;
                cs[nt * 2 + 1] += v1 + v3;
                bf16* Cb = (bf16*)Cv + (size_t)z * sCz;
                *(__nv_bfloat162*)&Cb[(size_t)r0 * N + col] =
                    __floats2bfloat162_rn(v0, v1);
                *(__nv_bfloat162*)&Cb[(size_t)(r0 + 8) * N + col] =
                    __floats2bfloat162_rn(v2, v3);
            } else if (EPI == 2) {
                bf16* Cb = (bf16*)Cv + (size_t)z * sCz;
                *(__nv_bfloat162*)&Cb[(size_t)r0 * N + col] =
                    __floats2bfloat162_rn(v0, v1);
                *(__nv_bfloat162*)&Cb[(size_t)(r0 + 8) * N + col] =
                    __floats2bfloat162_rn(v2, v3);
            } else if (EPI == 3) {
                float s0 = eg[col] * rsqrtf(ev[col] + 1e-5f);
                float h0 = eb[col] - em[col] * s0;
                float s1 = eg[col + 1] * rsqrtf(ev[col + 1] + 1e-5f);
                float h1 = eb[col + 1] - em[col + 1] * s1;
                const float* xin = zs ? RX1 : RX0;
                float* outp = (float*)Cv + (size_t)zs * BSZ * CIN * LSEQ;
                int b = r0 >> 10, hw = r0 & 1023;
                size_t p0 = ((size_t)b * CIN + col) * LSEQ + hw;
                size_t p1 = p0 + LSEQ;
                outp[p0]     = xin[p0]     + sg * (v0 * s0 + h0);
                outp[p1]     = xin[p1]     + sg * (v1 * s1 + h1);
                outp[p0 + 8] = xin[p0 + 8] + sg * (v2 * s0 + h0);
                outp[p1 + 8] = xin[p1 + 8] + sg * (v3 * s1 + h1);
            } else {
                float* Cf = (float*)Cv + (size_t)z * sCz;
                *(float2*)&Cf[(size_t)r0 * N + col]       = make_float2(v0, v1);
                *(float2*)&Cf[(size_t)(r0 + 8) * N + col] = make_float2(v2, v3);
            }
        }
    }

    if (EPI == 1) {
#pragma unroll
        for (int off = 4; off <= 16; off <<= 1)
#pragma unroll
            for (int i = 0; i < 16; i++)
                cs[i] += __shfl_xor_sync(0xffffffffu, cs[i], off);
        __syncthreads();
        float* scol = smf;
        if (wid < 2 && lane < 4) {
#pragma unroll
            for (int nt = 0; nt < 8; nt++) {
                scol[wn + nt * 8 + lane * 2]     = cs[nt * 2];
                scol[wn + nt * 8 + lane * 2 + 1] = cs[nt * 2 + 1];
            }
        }
        __syncthreads();
        if (wid >= 2 && lane < 4) {
#pragma unroll
            for (int nt = 0; nt < 8; nt++) {
                scol[wn + nt * 8 + lane * 2]     += cs[nt * 2];
                scol[wn + nt * 8 + lane * 2 + 1] += cs[nt * 2 + 1];
            }
        }
        __syncthreads();
        d_ppart[zs][m0 >> 7][n0 + tid] = scol[tid];
    }
}

// ---------------- mega prep ----------------
#define PREP_N (DM * CIN + CIN * DM + 2 * (2 * DI * DM))
#define NB_PREP (PREP_N / 256)
#define NB_TIN  (32 * 8 * 8)
#define NB_TW   (32 * 16 * 2)
__global__ void __launch_bounds__(256)
mega_prep(const float* __restrict__ crw, const float* __restrict__ crsw,
          const float* __restrict__ iw0, const float* __restrict__ iw1,
          const float* __restrict__ x0, const float* __restrict__ x1,
          const float* __restrict__ ow0, const float* __restrict__ ow1) {
    int bid = blockIdx.x;
    int tid = threadIdx.x;
    if (bid < NB_PREP) {
        int i = bid * 256 + tid;
        const int n1 = DM * CIN, n2 = n1 + CIN * DM, n3 = n2 + 2 * DI * DM;
        if (i < n1)       d_crw[i]           = __float2bfloat16(crw[i]);
        else if (i < n2)  d_crsw[i - n1]     = __float2bfloat16(crsw[i - n1]);
        else if (i < n3)  d_inw[0][i - n2]   = __float2bfloat16(iw0[i - n2]);
        else              d_inw[1][i - n3]   = __float2bfloat16(iw1[i - n3]);
    } else if (bid < NB_PREP + NB_TIN) {
        __shared__ float tile[32][33];
        int q = bid - NB_PREP;
        int zc = q >> 8;
        int s = zc >> 2, b = zc & 3;
        int rem = q & 255;
        int c0 = (rem >> 5) * 32, hw0 = (rem & 31) * 32;
        const float* x = s ? x1 : x0;
        int tx = tid & 31, ty = tid >> 5;
#pragma unroll
        for (int r = 0; r < 4; r++) {
            int row = ty + r * 8;
            tile[row][tx] = x[((size_t)b * CIN + (c0 + row)) * LSEQ + hw0 + tx];
        }
        __syncthreads();
#pragma unroll
        for (int r = 0; r < 4; r++) {
            int row = ty + r * 8;
            d_xt[s][((size_t)b * LSEQ + hw0 + row) * CIN + c0 + tx] =
                __float2bfloat16(tile[tx][row]);
        }
    } else {
        __shared__ float tile[32][33];
        int q = bid - NB_PREP - NB_TIN;
        int s = q >> 9;
        int rem = q & 511;
        int r0 = (rem >> 5) * 32, c0 = (rem & 31) * 32;
        const float* w = s ? ow1 : ow0;
        int tx = tid & 31, ty = tid >> 5;
#pragma unroll
        for (int r = 0; r < 4; r++) {
            int row = ty + r * 8;
            tile[row][tx] = w[(size_t)(r0 + row) * DI + c0 + tx];
        }
        __syncthreads();
#pragma unroll
        for (int r = 0; r < 4; r++) {
            int row = ty + r * 8;
            d_wt[s][(size_t)(c0 + row) * DM + r0 + tx] = __float2bfloat16(tile[tx][row]);
        }
    }
}

// ---------------- layernorm (warp/token) + wc_reduce + lambda, one launch ----------------
#define NB_LN  (2 * NTOK / 4)                // 2048
#define NB_WCR (2 * CIN * DI / 128)          // 4096
__global__ void __launch_bounds__(128)
poolln(const float* __restrict__ g0, const float* __restrict__ b0,
       const float* __restrict__ g1, const float* __restrict__ b1,
       const float* __restrict__ lw1, const float* __restrict__ lb1,
       const float* __restrict__ lw2, const float* __restrict__ lb2) {
    int bid = blockIdx.x;
    int t = threadIdx.x;
    if (bid < NB_LN) {
        int wid = t >> 5, lane = t & 31;
        int tok = bid * 4 + wid;
        int s = tok >> 12;
        int n = tok & (NTOK - 1);
        const float* g = s ? g1 : g0;
        const float* b = s ? b1 : b0;
        const __nv_bfloat162* src = (const __nv_bfloat162*)(d_seq[s] + (size_t)n * DM);
        float2 v[8];
        float sm = 0.f, sq = 0.f;
#pragma unroll
        for (int j = 0; j < 8; j++) {
            v[j] = __bfloat1622float2(src[lane + 32 * j]);
            sm += v[j].x + v[j].y;
            sq += v[j].x * v[j].x + v[j].y * v[j].y;
        }
#pragma unroll
        for (int o = 16; o; o >>= 1) {
            sm += __shfl_xor_sync(0xffffffffu, sm, o);
            sq += __shfl_xor_sync(0xffffffffu, sq, o);
        }
        float mu = sm * (1.f / DM);
        float var = sq * (1.f / DM) - mu * mu;
        float inv = rsqrtf(var + 1e-5f);
        __nv_bfloat162* dst = (__nv_bfloat162*)(d_xn[s] + (size_t)n * DM);
#pragma unroll
        for (int j = 0; j < 8; j++) {
            int p = lane + 32 * j;
            float2 gg = *(const float2*)&g[2 * p];
            float2 bb = *(const float2*)&b[2 * p];
            dst[p] = __floats2bfloat162_rn((v[j].x - mu) * inv * gg.x + bb.x,
                                           (v[j].y - mu) * inv * gg.y + bb.y);
        }
    } else if (bid < NB_LN + NB_WCR) {
        int idx = (bid - NB_LN) * 128 + t;
        int s = idx >> 18;
        int j = idx & (CIN * DI - 1);
        float v = d_wcp[s * 4 + 0][j] + d_wcp[s * 4 + 1][j] +
                  d_wcp[s * 4 + 2][j] + d_wcp[s * 4 + 3][j];
        d_wc[s][j] = __float2bfloat16(v);
    } else {
        // lambda predictor for batch b (4 blocks)
        int b = bid - NB_LN - NB_WCR;
        int j = t;
        __shared__ float pooled[2 * DM];
        for (int idx = j; idx < 2 * DM; idx += 128) {
            int s = idx >> 9, d = idx & (DM - 1);
            float acc = 0.f;
#pragma unroll
            for (int c = 0; c < 8; c++) acc += d_ppart[s][b * 8 + c][d];
            pooled[idx] = acc * (1.0f / LSEQ);
        }
        __syncthreads();
        const float* w = lw1 + (size_t)j * (2 * DM);
        float acc = lb1[j];
        for (int c = 0; c < DM; c++) acc += pooled[c] * w[c];
        for (int c = 0; c < DM; c++) acc += pooled[DM + c] * w[DM + c];
        __shared__ float h1[128];
        h1[j] = fmaxf(acc, 0.f);
        __syncthreads();
        if (j == 0) {
            float l0 = lb2[0], l1 = lb2[1];
            for (int c = 0; c < 128; c++) { l0 += h1[c] * lw2[c]; l1 += h1[c] * lw2[128 + c]; }
            float mx = fmaxf(l0, l1);
            float e0 = expf(l0 - mx), e1 = expf(l1 - mx);
            float inv = 1.f / (e0 + e1);
            d_lam[b * 2 + 0] = e0 * inv;
            d_lam[b * 2 + 1] = e1 * inv;
        }
    }
}

// ================= chunked parallel scan =================
__device__ __forceinline__ size_t hf_off(int s, int dir, int b, int c, int i) {
    return (((((size_t)s * 2 + dir) * 4 + b) * NCH + c) * DS) * 1024 + i;
}

__global__ void __launch_bounds__(256)
scan_pass1(const float* __restrict__ VA, const float* __restrict__ VB,
           const float* __restrict__ IA, const float* __restrict__ IB) {
    int idx = blockIdx.x * 256 + threadIdx.x;
    int i   = idx & 1023;
    int r   = idx >> 10;
    int c   = r % 7;
    int r2  = r / 7;
    int b   = r2 & 3;
    int dir = (r2 >> 2) & 1;
    int s   = (r2 >> 3) & 1;

    const float* Alog = s ? IA : VA;
    const float* Bown = s ? IB : VB;
    const float* Both = s ? VB : IB;
    float w0 = 0.5f * d_lam[b * 2 + 0];
    float w1 = 0.5f * d_lam[b * 2 + 1];

    u64 A2[8], Be2[8], h2[8];
#pragma unroll
    for (int k = 0; k < 8; k++) {
        float a0 = fminf(fmaxf(-expf(Alog[i * DS + 2 * k]),     -10.f), -0.01f);
        float a1 = fminf(fmaxf(-expf(Alog[i * DS + 2 * k + 1]), -10.f), -0.01f);
        A2[k]  = pack2(a0, a1);
        Be2[k] = pack2(w0 * Bown[i * DS + 2 * k]     + w1 * Both[i * DS + 2 * k],
                       w0 * Bown[i * DS + 2 * k + 1] + w1 * Both[i * DS + 2 * k + 1]);
        h2[k] = 0ull;
    }

    const bf16* xs = d_xp[s] + (size_t)b * LSEQ * (2 * DI) + i;
    int t  = dir ? (LSEQ - 1 - c * CHL) : c * CHL;
    int dt = dir ? -1 : 1;

    for (int step = 0; step < CHL; step++, t += dt) {
        float x = __bfloat162float(xs[(size_t)t * (2 * DI)]);
        u64 xd = pack2(x, x);
#pragma unroll
        for (int k = 0; k < 8; k++)
            h2[k] = fma2_(h2[k], A2[k], fma2_(Be2[k], xd, 0ull));
    }

    size_t o0 = hf_off(s, dir, b, c, i);
#pragma unroll
    for (int k = 0; k < 8; k++) {
        float2 f = unpack2(h2[k]);
        d_hfin[o0 + (size_t)(2 * k) * 1024]     = f.x;
        d_hfin[o0 + (size_t)(2 * k + 1) * 1024] = f.y;
    }
}

__global__ void __launch_bounds__(256, 2)
scan_pass3m(const float* __restrict__ VA, const float* __restrict__ VB,
            const float* __restrict__ VC, const float* __restrict__ IA,
            const float* __restrict__ IB, const float* __restrict__ IC) {
    extern __shared__ bf16 yfs[];
    int tid = threadIdx.x;
    int idx = blockIdx.x * 256 + tid;
    int i   = idx & 1023;
    int c   = (idx >> 10) & 7;
    int b   = (idx >> 13) & 3;
    int s   = (idx >> 14) & 1;

    const float* Alog = s ? IA : VA;
    const float* Bown = s ? IB : VB;
    const float* Both = s ? VB : IB;
    const float* Cp   = s ? IC : VC;
    float w0 = 0.5f * d_lam[b * 2 + 0];
    float w1 = 0.5f * d_lam[b * 2 + 1];

    u64 A2[8], Be2[8], C2[8], h2[8];
#pragma unroll
    for (int k = 0; k < 8; k++) {
        float a0 = fminf(fmaxf(-expf(Alog[i * DS + 2 * k]),     -10.f), -0.01f);
        float a1 = fminf(fmaxf(-expf(Alog[i * DS + 2 * k + 1]), -10.f), -0.01f);
        A2[k]  = pack2(a0, a1);
        Be2[k] = pack2(w0 * Bown[i * DS + 2 * k]     + w1 * Both[i * DS + 2 * k],
                       w0 * Bown[i * DS + 2 * k + 1] + w1 * Both[i * DS + 2 * k + 1]);
        C2[k]  = pack2(Cp[i * DS + 2 * k], Cp[i * DS + 2 * k + 1]);
    }

    u64 a128[8];
#pragma unroll
    for (int k = 0; k < 8; k++) {
        u64 a = A2[k];
#pragma unroll
        for (int q = 0; q < 7; q++) a = fma2_(a, a, 0ull);
        a128[k] = a;
    }

    const bf16* xs = d_xp[s] + (size_t)b * LSEQ * (2 * DI) + i;
    const bf16* gs = xs + DI;
    bf16* uo = d_u[s] + (size_t)b * LSEQ * DI + i;
    const int t0 = c * CHL;
    const int cb = NCH - 1 - c;

    {
#pragma unroll
        for (int k = 0; k < 8; k++) h2[k] = 0ull;
        for (int cc = 0; cc < c; cc++) {
            size_t o = hf_off(s, 0, b, cc, i);
#pragma unroll
            for (int k = 0; k < 8; k++) {
                u64 fin = pack2(d_hfin[o + (size_t)(2 * k) * 1024],
                                d_hfin[o + (size_t)(2 * k + 1) * 1024]);
                h2[k] = fma2_(h2[k], a128[k], fin);
            }
        }
        for (int step = 0; step < CHL; step++) {
            float x = __bfloat162float(xs[(size_t)(t0 + step) * (2 * DI)]);
            u64 xd = pack2(x, x);
            u64 yp = 0ull;
#pragma unroll
            for (int k = 0; k < 8; k++) {
                h2[k] = fma2_(h2[k], A2[k], fma2_(Be2[k], xd, 0ull));
                yp = fma2_(h2[k], C2[k], yp);
            }
            float2 f = unpack2(yp);
            yfs[step * 256 + tid] = __float2bfloat16(f.x + f.y);
        }
    }
    {
#pragma unroll
        for (int k = 0; k < 8; k++) h2[k] = 0ull;
        for (int cc = 0; cc < cb; cc++) {
            size_t o = hf_off(s, 1, b, cc, i);
#pragma unroll
            for (int k = 0; k < 8; k++) {
                u64 fin = pack2(d_hfin[o + (size_t)(2 * k) * 1024],
                                d_hfin[o + (size_t)(2 * k + 1) * 1024]);
                h2[k] = fma2_(h2[k], a128[k], fin);
            }
        }
        for (int step = 0; step < CHL; step++) {
            int ls = CHL - 1 - step;
            int t = t0 + ls;
            float x = __bfloat162float(xs[(size_t)t * (2 * DI)]);
            u64 xd = pack2(x, x);
            u64 yp = 0ull;
#pragma unroll
            for (int k = 0; k < 8; k++) {
                h2[k] = fma2_(h2[k], A2[k], fma2_(Be2[k], xd, 0ull));
                yp = fma2_(h2[k], C2[k], yp);
            }
            float2 f = unpack2(yp);
            float yb = f.x + f.y;
            float yf = __bfloat162float(yfs[ls * 256 + tid]);
            float g = __bfloat162float(gs[(size_t)t * (2 * DI)]);
            float sig = 1.f / (1.f + expf(-g));
            uo[(size_t)t * DI] = __float2bfloat16((yf + yb) * g * sig);
        }
    }
}

// ---------------- launch ----------------
extern "C" void kernel_launch(void* const* d_in, const int* in_sizes, int n_in,
                              void* d_out, int out_size) {
    const float* x_V        = (const float*)d_in[0];
    const float* x_I        = (const float*)d_in[1];
    const float* conv_red_w = (const float*)d_in[2];
    const float* bn_red_g   = (const float*)d_in[3];
    const float* bn_red_b   = (const float*)d_in[4];
    const float* bn_red_m   = (const float*)d_in[5];
    const float* bn_red_v   = (const float*)d_in[6];
    const float* conv_res_w = (const float*)d_in[7];
    const float* bn_res_g   = (const float*)d_in[8];
    const float* bn_res_b   = (const float*)d_in[9];
    const float* bn_res_m   = (const float*)d_in[10];
    const float* bn_res_v   = (const float*)d_in[11];
    const float* lam_w1     = (const float*)d_in[12];
    const float* lam_b1     = (const float*)d_in[13];
    const float* lam_w2     = (const float*)d_in[14];
    const float* lam_b2     = (const float*)d_in[15];
    const float* in_w[2]    = {(const float*)d_in[16], (const float*)d_in[23]};
    const float* out_w[2]   = {(const float*)d_in[17], (const float*)d_in[24]};
    const float* A_log[2]   = {(const float*)d_in[18], (const float*)d_in[25]};
    const float* Bmat[2]    = {(const float*)d_in[19], (const float*)d_in[26]};
    const float* Cmat[2]    = {(const float*)d_in[20], (const float*)d_in[27]};
    const float* ln_g[2]    = {(const float*)d_in[21], (const float*)d_in[28]};
    const float* ln_b[2]    = {(const float*)d_in[22], (const float*)d_in[29]};
    const float* gate       = (const float*)d_in[30];

    bf16 *XT, *SEQ, *XN, *XP, *U, *WT, *WC, *CRW, *CRSW, *INW;
    float *WCP;
    cudaGetSymbolAddress((void**)&XT,   d_xt);
    cudaGetSymbolAddress((void**)&SEQ,  d_seq);
    cudaGetSymbolAddress((void**)&XN,   d_xn);
    cudaGetSymbolAddress((void**)&XP,   d_xp);
    cudaGetSymbolAddress((void**)&U,    d_u);
    cudaGetSymbolAddress((void**)&WT,   d_wt);
    cudaGetSymbolAddress((void**)&WC,   d_wc);
    cudaGetSymbolAddress((void**)&WCP,  d_wcp);
    cudaGetSymbolAddress((void**)&CRW,  d_crw);
    cudaGetSymbolAddress((void**)&CRSW, d_crsw);
    cudaGetSymbolAddress((void**)&INW,  d_inw);

    cudaFuncSetAttribute(tgemm<0>, cudaFuncAttributeMaxDynamicSharedMemorySize, TG_SMEM);
    cudaFuncSetAttribute(tgemm<1>, cudaFuncAttributeMaxDynamicSharedMemorySize, TG_SMEM);
    cudaFuncSetAttribute(tgemm<2>, cudaFuncAttributeMaxDynamicSharedMemorySize, TG_SMEM);
    cudaFuncSetAttribute(tgemm<3>, cudaFuncAttributeMaxDynamicSharedMemorySize, TG_SMEM);
    cudaFuncSetAttribute(scan_pass3m, cudaFuncAttributeMaxDynamicSharedMemorySize, 65536);

    // 0. mega prep
    mega_prep<<<NB_PREP + NB_TIN + NB_TW, 256>>>(
        conv_red_w, conv_res_w, in_w[0], in_w[1], x_V, x_I, out_w[0], out_w[1]);

    // 1. Wc split-K x4 (reduce folded into poolln)
    tgemm<0><<<dim3(DI / 128, CIN / 128, 8), 128, TG_SMEM>>>(
        CRSW, CRSW, WT, WT + (size_t)DI * DM, WCP, CIN, DI, DM / 4, DM, DM, 4,
        (long long)CIN * DI, nullptr, nullptr, nullptr, nullptr,
        nullptr, nullptr, nullptr);

    // 2. conv_red + BN + ReLU -> bf16 d_seq (+ fused column pool partials)
    tgemm<1><<<dim3(DM / 128, NTOK / 128, 2), 128, TG_SMEM>>>(
        XT, XT + (size_t)NTOK * CIN, CRW, CRW, SEQ, NTOK, DM, CIN, CIN, CIN, 1,
        (long long)NTOK * DM, bn_red_g, bn_red_b, bn_red_m, bn_red_v,
        nullptr, nullptr, nullptr);

    // 3. layernorm + wc_reduce + lambda, one launch
    poolln<<<NB_LN + NB_WCR + 4, 128>>>(ln_g[0], ln_b[0], ln_g[1], ln_b[1],
                                        lam_w1, lam_b1, lam_w2, lam_b2);

    // 4. in_proj (bf16 out)
    tgemm<2><<<dim3(2 * DI / 128, NTOK / 128, 2), 128, TG_SMEM>>>(
        XN, XN + (size_t)NTOK * DM, INW, INW + (size_t)2 * DI * DM, XP, NTOK, 2 * DI,
        DM, DM, DM, 1, (long long)NTOK * 2 * DI, nullptr, nullptr, nullptr, nullptr,
        nullptr, nullptr, nullptr);

    // 5. scan
    scan_pass1<<<448, 256>>>(A_log[0], Bmat[0], A_log[1], Bmat[1]);
    scan_pass3m<<<256, 256, 65536>>>(A_log[0], Bmat[0], Cmat[0],
                                     A_log[1], Bmat[1], Cmat[1]);

    // 6. fused out_proj + conv_res + BN + residual + gate -> output
    tgemm<3><<<dim3(CIN / 128, NTOK / 128, 2), 128, TG_SMEM>>>(
        U, U + (size_t)NTOK * DI, WC, WC + (size_t)CIN * DI, (float*)d_out, NTOK, CIN,
        DI, DI, DI, 1, 0LL, bn_res_g, bn_res_b, bn_res_m, bn_res_v,
        x_V, x_I, gate);
}